// round 1
// baseline (speedup 1.0000x reference)
#include <cuda_runtime.h>
#include <cuda_bf16.h>
#include <cstdint>

#define N_PTS 384
#define DIM 128
#define MARGIN 0.3f

// Scratch for the pairwise distance matrix (no allocations allowed).
__device__ float g_dist[N_PTS * N_PTS];

// ---------------------------------------------------------------------------
// K1: pairwise squared-euclidean distances, 32x32 tiles, smem-staged.
// grid (12,12), block 256 threads. dist(i,j) = sum_k (E[i,k]-E[j,k])^2
// ---------------------------------------------------------------------------
__global__ __launch_bounds__(256) void dist_kernel(const float* __restrict__ E,
                                                   float* __restrict__ dist) {
    // 32 rows x 128 cols, padded to 132 floats (multiple of 4 for float4,
    // 132 % 32 == 4 -> at most 2-way bank conflicts on the B reads).
    __shared__ float As[32][132];
    __shared__ float Bs[32][132];

    const int bi = blockIdx.y * 32;
    const int bj = blockIdx.x * 32;
    const int t = threadIdx.x;

    // Cooperative load: 32 rows x 32 float4 = 1024 float4 per tile.
    const float4* E4 = reinterpret_cast<const float4*>(E);
    for (int v = t; v < 1024; v += 256) {
        int r = v >> 5;        // row in tile
        int c4 = v & 31;       // float4 column
        float4 a = E4[(bi + r) * 32 + c4];
        float4 b = E4[(bj + r) * 32 + c4];
        *reinterpret_cast<float4*>(&As[r][c4 * 4]) = a;
        *reinterpret_cast<float4*>(&Bs[r][c4 * 4]) = b;
    }
    __syncthreads();

    // 2x2 register tile per thread: rows {ti, ti+16}, cols {tj, tj+16}.
    const int ti = t >> 4;
    const int tj = t & 15;

    float acc00 = 0.f, acc01 = 0.f, acc10 = 0.f, acc11 = 0.f;

#pragma unroll 8
    for (int k4 = 0; k4 < 32; k4++) {
        float4 a0 = *reinterpret_cast<const float4*>(&As[ti][k4 * 4]);
        float4 a1 = *reinterpret_cast<const float4*>(&As[ti + 16][k4 * 4]);
        float4 b0 = *reinterpret_cast<const float4*>(&Bs[tj][k4 * 4]);
        float4 b1 = *reinterpret_cast<const float4*>(&Bs[tj + 16][k4 * 4]);
        float d;
        d = a0.x - b0.x; acc00 = fmaf(d, d, acc00);
        d = a0.y - b0.y; acc00 = fmaf(d, d, acc00);
        d = a0.z - b0.z; acc00 = fmaf(d, d, acc00);
        d = a0.w - b0.w; acc00 = fmaf(d, d, acc00);
        d = a0.x - b1.x; acc01 = fmaf(d, d, acc01);
        d = a0.y - b1.y; acc01 = fmaf(d, d, acc01);
        d = a0.z - b1.z; acc01 = fmaf(d, d, acc01);
        d = a0.w - b1.w; acc01 = fmaf(d, d, acc01);
        d = a1.x - b0.x; acc10 = fmaf(d, d, acc10);
        d = a1.y - b0.y; acc10 = fmaf(d, d, acc10);
        d = a1.z - b0.z; acc10 = fmaf(d, d, acc10);
        d = a1.w - b0.w; acc10 = fmaf(d, d, acc10);
        d = a1.x - b1.x; acc11 = fmaf(d, d, acc11);
        d = a1.y - b1.y; acc11 = fmaf(d, d, acc11);
        d = a1.z - b1.z; acc11 = fmaf(d, d, acc11);
        d = a1.w - b1.w; acc11 = fmaf(d, d, acc11);
    }

    const int gi0 = bi + ti, gi1 = bi + ti + 16;
    const int gj0 = bj + tj, gj1 = bj + tj + 16;
    dist[gi0 * N_PTS + gj0] = acc00;
    dist[gi0 * N_PTS + gj1] = acc01;
    dist[gi1 * N_PTS + gj0] = acc10;
    dist[gi1 * N_PTS + gj1] = acc11;
}

// ---------------------------------------------------------------------------
// K2: per-anchor triplet accumulation.
// One block per anchor i. Split the row into positive/negative distance lists
// (positives include j==i, matching the reference mask), then brute-force all
// (p, n) pairs: L = dp - dn + MARGIN, valid iff 0 < L < MARGIN.
// ---------------------------------------------------------------------------
__global__ __launch_bounds__(256) void triplet_kernel(const float* __restrict__ dist,
                                                      const int* __restrict__ labels,
                                                      float* __restrict__ out) {
    const int i = blockIdx.x;
    const int t = threadIdx.x;

    __shared__ float spos[N_PTS];
    __shared__ float sneg[N_PTS];
    __shared__ int cnts[2];           // [0]=P, [1]=M
    __shared__ float wl[8], wc[8];    // per-warp partials

    if (t < 2) cnts[t] = 0;
    __syncthreads();

    const int li = labels[i];
    const float* drow = dist + i * N_PTS;

    for (int j = t; j < N_PTS; j += 256) {
        int lj = labels[j];
        float dj = drow[j];
        if (lj == li) {
            int idx = atomicAdd(&cnts[0], 1);
            spos[idx] = dj;
        } else {
            int idx = atomicAdd(&cnts[1], 1);
            sneg[idx] = dj;
        }
    }
    __syncthreads();

    const int P = cnts[0];
    const int M = cnts[1];

    float loss = 0.f;
    float cnt = 0.f;
    for (int p = 0; p < P; p++) {
        const float dp = spos[p];
        for (int n = t; n < M; n += 256) {
            float L = (dp - sneg[n]) + MARGIN;
            if (L > 0.f && L < MARGIN) {
                loss += L;
                cnt += 1.f;
            }
        }
    }

    // Block reduction.
    const int lane = t & 31;
    const int warp = t >> 5;
#pragma unroll
    for (int off = 16; off > 0; off >>= 1) {
        loss += __shfl_down_sync(0xFFFFFFFFu, loss, off);
        cnt  += __shfl_down_sync(0xFFFFFFFFu, cnt,  off);
    }
    if (lane == 0) { wl[warp] = loss; wc[warp] = cnt; }
    __syncthreads();
    if (warp == 0) {
        float l = (lane < 8) ? wl[lane] : 0.f;
        float c = (lane < 8) ? wc[lane] : 0.f;
#pragma unroll
        for (int off = 4; off > 0; off >>= 1) {
            l += __shfl_down_sync(0xFFFFFFFFu, l, off);
            c += __shfl_down_sync(0xFFFFFFFFu, c, off);
        }
        if (lane == 0) {
            atomicAdd(&out[0], l);
            atomicAdd(&out[1], c);
        }
    }
}

extern "C" void kernel_launch(void* const* d_in, const int* in_sizes, int n_in,
                              void* d_out, int out_size) {
    const float* embeddings = (const float*)d_in[0];
    const int* labels = (const int*)d_in[1];
    float* out = (float*)d_out;

    cudaMemsetAsync(out, 0, (size_t)out_size * sizeof(float));

    float* dist;
    cudaGetSymbolAddress((void**)&dist, g_dist);

    dim3 grid1(12, 12);
    dist_kernel<<<grid1, 256>>>(embeddings, dist);

    triplet_kernel<<<N_PTS, 256>>>(dist, labels, out);
}